// round 9
// baseline (speedup 1.0000x reference)
#include <cuda_runtime.h>

// Dykstra alternating projection, n=4096, up to 20 iterations.
//   Xp = X + (1/n + s/n^2) - row_i/n - col_j/n ;  X <- relu(Xp)
//   freeze X once min(Xp) >= 0  (relu(Xp)==Xp in that case)
//
// R8 -> R9: remove all __syncthreads from the hot row loop (was 16/block via
// per-row blockReduceSum; now 2 total). Per-thread rp[8] accumulators +
// warp-shuffle reductions let the 32 float4 loads of a block's 8 rows pipeline
// (MLP ~16-32 instead of ~4), attacking the latency-bound profile
// (issue=15%, all mem pipes ~24%).

#define NDIM 4096
#define RPB 8                         // rows per block
#define NBLK (NDIM / RPB)             // 512 blocks
#define NTHREADS 256
#define NWARPS (NTHREADS / 32)        // 8
#define MAXIT 20
#define F4_PER_ROW (NDIM / 4)         // 1024 float4 per row
#define FPT (F4_PER_ROW / NTHREADS)   // 4 float4 per thread per row
#define F4_ZERO_PER_BLK (F4_PER_ROW / NBLK)   // 2

__device__ float  g_row[NDIM];              // row sums (exclusive per block -> plain stores)
__device__ float4 g_col[3][F4_PER_ROW];     // col sums, triple-buffered
__device__ float  g_total[MAXIT + 1];       // per-iteration totals (atomic accum, pre-zeroed)
__device__ int    g_neg[MAXIT];             // any-negative flag per iteration

__global__ void init_kernel() {
    int t = threadIdx.x;
    for (int i = t; i < F4_PER_ROW; i += NTHREADS) {
        g_col[0][i] = make_float4(0.f, 0.f, 0.f, 0.f);
        g_col[1][i] = make_float4(0.f, 0.f, 0.f, 0.f);
    }
    if (t <= MAXIT) g_total[t] = 0.f;
    if (t < MAXIT)  g_neg[t] = 0;
}

__device__ __forceinline__ float warpReduceSum(float v) {
    #pragma unroll
    for (int o = 16; o > 0; o >>= 1) v += __shfl_down_sync(0xffffffffu, v, o);
    return v;
}

// Pre-pass: row/col/total sums of the initial X (input for iteration 0).
__global__ __launch_bounds__(NTHREADS)
void reduce0_kernel(const float* __restrict__ X) {
    __shared__ float s_part[NWARPS][RPB];
    __shared__ float s_rs[RPB];
    int t = threadIdx.x;
    int lane = t & 31, wid = t >> 5;
    int row0 = blockIdx.x * RPB;

    float4 cacc[FPT];
    #pragma unroll
    for (int g = 0; g < FPT; g++) cacc[g] = make_float4(0.f, 0.f, 0.f, 0.f);
    float rp[RPB];
    #pragma unroll
    for (int r = 0; r < RPB; r++) rp[r] = 0.f;

    #pragma unroll
    for (int r = 0; r < RPB; r++) {
        const float4* xr = (const float4*)(X + (size_t)(row0 + r) * NDIM);
        #pragma unroll
        for (int g = 0; g < FPT; g++) {
            float4 v = xr[t + NTHREADS * g];
            rp[r] += (v.x + v.y) + (v.z + v.w);
            cacc[g].x += v.x; cacc[g].y += v.y; cacc[g].z += v.z; cacc[g].w += v.w;
        }
    }

    #pragma unroll
    for (int r = 0; r < RPB; r++) {
        float v = warpReduceSum(rp[r]);
        if (lane == 0) s_part[wid][r] = v;
    }
    __syncthreads();
    if (t < RPB) {
        float rs = 0.f;
        #pragma unroll
        for (int w = 0; w < NWARPS; w++) rs += s_part[w][t];
        g_row[row0 + t] = rs;
        s_rs[t] = rs;
    }
    __syncthreads();
    if (t == 0) {
        float bt = 0.f;
        #pragma unroll
        for (int r = 0; r < RPB; r++) bt += s_rs[r];
        atomicAdd(&g_total[0], bt);
    }
    #pragma unroll
    for (int g = 0; g < FPT; g++) {
        int i = t + NTHREADS * g;
        atomicAdd(&g_col[0][i].x, cacc[g].x);
        atomicAdd(&g_col[0][i].y, cacc[g].y);
        atomicAdd(&g_col[0][i].z, cacc[g].z);
        atomicAdd(&g_col[0][i].w, cacc[g].w);
    }
}

// Iteration k: update X (in place after k=0) + reductions for iteration k+1.
__global__ __launch_bounds__(NTHREADS)
void fused_kernel(const float* __restrict__ Xin, float* __restrict__ Xout,
                  int k, const int* __restrict__ max_iters) {
    __shared__ float s_part[NWARPS][RPB];
    __shared__ float s_rs[RPB];
    __shared__ float s_rowsub[RPB];
    __shared__ int s_done;
    int t = threadIdx.x;
    int lane = t & 31, wid = t >> 5;
    int row0 = blockIdx.x * RPB;

    // Parallel done-check (warp ballot over prior iterations' neg flags)
    // while another warp fetches the row subtractors.
    if (t < 32) {
        int z = (t < k) ? (g_neg[t] == 0) : 0;
        unsigned m = __ballot_sync(0xffffffffu, z);
        if (t == 0) s_done = (m != 0u) || (k >= *max_iters);
    }
    if (t >= 32 && t < 32 + RPB)
        s_rowsub[t - 32] = g_row[row0 + (t - 32)] * (1.0f / NDIM);
    __syncthreads();

    if (s_done) {
        if (k == 0) {  // max_iters==0: output = input (never hit for 20)
            #pragma unroll
            for (int r = 0; r < RPB; r++) {
                const float4* xr = (const float4*)(Xin + (size_t)(row0 + r) * NDIM);
                float4*       yr = (float4*)(Xout + (size_t)(row0 + r) * NDIM);
                #pragma unroll
                for (int g = 0; g < FPT; g++)
                    yr[t + NTHREADS * g] = xr[t + NTHREADS * g];
            }
        }
        return;
    }

    const float inv_n = 1.0f / NDIM;
    float total = g_total[k];                 // uniform load, L2 broadcast
    float c = inv_n + total * inv_n * inv_n;

    int rdc = k % 3, wrc = (k + 1) % 3, zc = (k + 2) % 3;

    // Zero the buffer iteration k+1 accumulates into (dead since k-1); issue
    // early so the stores retire under the main loop.
    if (t < F4_ZERO_PER_BLK)
        g_col[zc][blockIdx.x * F4_ZERO_PER_BLK + t] = make_float4(0.f, 0.f, 0.f, 0.f);

    // Hoist this thread's col values (pre-scaled) — reused across all RPB rows.
    float4 cvn[FPT];
    #pragma unroll
    for (int g = 0; g < FPT; g++) {
        float4 cv = g_col[rdc][t + NTHREADS * g];
        cvn[g] = make_float4(cv.x * inv_n, cv.y * inv_n, cv.z * inv_n, cv.w * inv_n);
    }

    float4 cacc[FPT];
    #pragma unroll
    for (int g = 0; g < FPT; g++) cacc[g] = make_float4(0.f, 0.f, 0.f, 0.f);
    float rp[RPB];
    #pragma unroll
    for (int r = 0; r < RPB; r++) rp[r] = 0.f;
    bool neg = false;

    // Hot loop: NO barriers -> loads across rows pipeline freely.
    #pragma unroll
    for (int r = 0; r < RPB; r++) {
        const float4* xr = (const float4*)(Xin + (size_t)(row0 + r) * NDIM);
        float4*       yr = (float4*)(Xout + (size_t)(row0 + r) * NDIM);
        float a = c - s_rowsub[r];
        #pragma unroll
        for (int g = 0; g < FPT; g++) {
            int i = t + NTHREADS * g;
            float4 v = xr[i];
            float4 xp;
            xp.x = v.x + a - cvn[g].x;
            xp.y = v.y + a - cvn[g].y;
            xp.z = v.z + a - cvn[g].z;
            xp.w = v.w + a - cvn[g].w;
            float mn = fminf(fminf(xp.x, xp.y), fminf(xp.z, xp.w));
            neg = neg || (mn < 0.f);
            float4 y;
            y.x = fmaxf(xp.x, 0.f); y.y = fmaxf(xp.y, 0.f);
            y.z = fmaxf(xp.z, 0.f); y.w = fmaxf(xp.w, 0.f);
            yr[i] = y;
            rp[r] += (y.x + y.y) + (y.z + y.w);
            cacc[g].x += y.x; cacc[g].y += y.y; cacc[g].z += y.z; cacc[g].w += y.w;
        }
    }

    // Row sums: warp-level (barrier-free), then one cross-warp pass.
    #pragma unroll
    for (int r = 0; r < RPB; r++) {
        float v = warpReduceSum(rp[r]);
        if (lane == 0) s_part[wid][r] = v;
    }

    // Col partials + total (REDG, no return) — independent of the barriers below.
    #pragma unroll
    for (int g = 0; g < FPT; g++) {
        int i = t + NTHREADS * g;
        atomicAdd(&g_col[wrc][i].x, cacc[g].x);
        atomicAdd(&g_col[wrc][i].y, cacc[g].y);
        atomicAdd(&g_col[wrc][i].z, cacc[g].z);
        atomicAdd(&g_col[wrc][i].w, cacc[g].w);
    }

    // Neg flag: one store per warp that saw a negative (barrier-free).
    if (__any_sync(0xffffffffu, neg)) {
        if (lane == 0) g_neg[k] = 1;
    }

    __syncthreads();
    if (t < RPB) {
        float rs = 0.f;
        #pragma unroll
        for (int w = 0; w < NWARPS; w++) rs += s_part[w][t];
        g_row[row0 + t] = rs;
        s_rs[t] = rs;
    }
    __syncthreads();
    if (t == 0) {
        float bt = 0.f;
        #pragma unroll
        for (int r = 0; r < RPB; r++) bt += s_rs[r];
        atomicAdd(&g_total[k + 1], bt);
    }
}

extern "C" void kernel_launch(void* const* d_in, const int* in_sizes, int n_in,
                              void* d_out, int out_size) {
    const float* X = (const float*)d_in[0];
    const int* max_iters = (const int*)d_in[1];
    float* out = (float*)d_out;
    (void)in_sizes; (void)n_in; (void)out_size;

    init_kernel<<<1, NTHREADS>>>();
    reduce0_kernel<<<NBLK, NTHREADS>>>(X);
    for (int k = 0; k < MAXIT; k++) {
        const float* src = (k == 0) ? X : out;
        fused_kernel<<<NBLK, NTHREADS>>>(src, out, k, max_iters);
    }
}